// round 2
// baseline (speedup 1.0000x reference)
#include <cuda_runtime.h>
#include <cstdint>

// Problem constants (fixed by reference)
#define RDIM 4096
#define TLEN 2048
#define IDIM 8
#define ODIM 8
#define MAXNNZ 640                 // Binomial(4096,0.1): mean ~410, sd ~19
#define NITER_MAX (MAXNNZ / 16)    // 40: iters at 16 lanes per row
#define NBLK 128                   // persistent CTAs, <= 148 SMs -> co-resident
#define NTHR 512                   // 16 warps
#define ROWS_PER_CTA (RDIM / NBLK) // 32
#define SLOTS_PER_CTA 16           // 2 rows per warp-slot

struct __align__(8) Ent { float v; int c; };

// Scratch (device globals: no allocation allowed)
__device__ Ent      g_ellw[RDIM / 2 * NITER_MAX * 32];   // ~21 MB, warp-interleaved
__device__ int      g_witer[RDIM];                       // ceil(nnz/16) per row
__device__ float    g_u[TLEN * RDIM];                    // Win @ x_t, all t (32 MB)
__device__ __align__(16) float g_h[2][RDIM];             // ping-pong hidden state
__device__ __align__(16) float g_woutT[RDIM * ODIM];     // Wout transposed
__device__ unsigned g_flags[NBLK];                       // barrier flags

// Strong gpu-scope ops that do NOT flush L1 (no CCTL.IVALL, unlike __threadfence)
__device__ __forceinline__ unsigned ld_acq(const unsigned* p) {
    unsigned v;
    asm volatile("ld.acquire.gpu.global.u32 %0, [%1];" : "=r"(v) : "l"(p) : "memory");
    return v;
}
__device__ __forceinline__ void st_rel(unsigned* p, unsigned v) {
    asm volatile("st.release.gpu.global.u32 [%0], %1;" :: "l"(p), "r"(v) : "memory");
}

// ---------------------------------------------------------------------------
// K1: u[t][r] = sum_i Win[r,i] * x[t,i]
// ---------------------------------------------------------------------------
__global__ void k_u(const float* __restrict__ x, const float* __restrict__ Win) {
    int t = blockIdx.x;
    __shared__ float xs[IDIM];
    if (threadIdx.x < IDIM) xs[threadIdx.x] = x[t * IDIM + threadIdx.x];
    __syncthreads();
    for (int r = threadIdx.x; r < RDIM; r += blockDim.x) {
        const float4* w = (const float4*)(Win + r * IDIM);
        float4 a = __ldg(&w[0]), b = __ldg(&w[1]);
        float s = a.x * xs[0] + a.y * xs[1] + a.z * xs[2] + a.w * xs[3]
                + b.x * xs[4] + b.y * xs[5] + b.z * xs[6] + b.w * xs[7];
        g_u[t * RDIM + r] = s;
    }
}

// ---------------------------------------------------------------------------
// K2: compact W rows into warp-interleaved ELL.
// Slot s holds rows 2s (lanes 0-15) and 2s+1 (lanes 16-31); iteration k of the
// consumer warp loads entries [s*NITER_MAX*32 + k*32 + lane] fully coalesced.
// Zero-padded so the consumer loop needs no per-lane bounds check.
// ---------------------------------------------------------------------------
__global__ void k_sparse(const float* __restrict__ W) {
    int row  = (blockIdx.x * blockDim.x + threadIdx.x) >> 5;
    int lane = threadIdx.x & 31;
    if (row >= RDIM) return;
    int s = row >> 1, half = row & 1;
    Ent* base = g_ellw + (size_t)s * (NITER_MAX * 32) + half * 16;

    // zero own half-slot (padding)
    for (int idx = lane; idx < NITER_MAX * 16; idx += 32) {
        int k = idx >> 4, j = idx & 15;
        base[k * 32 + j] = Ent{0.0f, 0};
    }
    __syncwarp();

    const float* wr = W + (size_t)row * RDIM;
    int cnt = 0;
    for (int c0 = 0; c0 < RDIM; c0 += 32) {
        float v = wr[c0 + lane];
        unsigned bal = __ballot_sync(0xffffffffu, v != 0.0f);
        if (v != 0.0f) {
            int pos = cnt + __popc(bal & ((1u << lane) - 1u));
            if (pos < NITER_MAX * 16) {
                int k = pos >> 4, j = pos & 15;
                base[k * 32 + j] = Ent{v, c0 + lane};
            }
        }
        cnt += __popc(bal);
    }
    if (lane == 0) {
        int it = (cnt + 15) >> 4;
        g_witer[row] = it < NITER_MAX ? it : NITER_MAX;
    }
}

// ---------------------------------------------------------------------------
// K3: per-replay init. Zero h, reset flags, seed out with bias, transpose Wout.
// ---------------------------------------------------------------------------
__global__ void k_init(float* __restrict__ out, const float* __restrict__ bias,
                       const float* __restrict__ Wout) {
    int i = blockIdx.x * blockDim.x + threadIdx.x;
    if (i < TLEN * ODIM) out[i] = bias[i & (ODIM - 1)];
    if (i < 2 * RDIM) ((float*)g_h)[i] = 0.0f;
    if (i < RDIM) {
#pragma unroll
        for (int o = 0; o < ODIM; o++)
            g_woutT[i * ODIM + o] = Wout[o * RDIM + i];
    }
    if (i < NBLK) g_flags[i] = 0u;
}

// ---------------------------------------------------------------------------
// K4: persistent recurrence. 128 CTAs x 512 threads. Per warp: 2 rows,
// 16 lanes each. Fence-free flag barrier keeps L1 warm (no CCTL.IVALL).
// ---------------------------------------------------------------------------
__global__ void __launch_bounds__(NTHR, 1)
k_main(float* __restrict__ out) {
    __shared__ float sh[RDIM];          // 16 KB: h_{t-1}
    __shared__ float ybuf[2 * SLOTS_PER_CTA][ODIM];

    const int tid  = threadIdx.x;
    const int wid  = tid >> 5;
    const int lane = tid & 31;
    const int slot = blockIdx.x * SLOTS_PER_CTA + wid;   // global warp-slot
    const int half = lane >> 4;                          // 0: row 2s, 1: row 2s+1
    const int row  = 2 * slot + half;

    // hoisted per-warp constants
    int ni = max(g_witer[2 * slot], g_witer[2 * slot + 1]);
    ni = (ni + 1) & ~1;                                  // even for dual-acc
    const Ent* ep = g_ellw + (size_t)slot * (NITER_MAX * 32) + lane;
    const bool head = (lane == 0) | (lane == 16);
    float w_y[ODIM];
    if (head) {
#pragma unroll
        for (int o = 0; o < ODIM; o++) w_y[o] = g_woutT[row * ODIM + o];
    }

    for (int t = 0; t < TLEN; ++t) {
        const float* hp = g_h[t & 1];
        float* hn = g_h[(t + 1) & 1];

        // stage h_{t-1} into SMEM (L2-direct: other CTAs wrote it via stcg)
        {
            int i = tid * 4;
            float4 v0 = __ldcg((const float4*)(hp + i));
            float4 v1 = __ldcg((const float4*)(hp + i + NTHR * 4));
            *(float4*)(sh + i) = v0;
            *(float4*)(sh + i + NTHR * 4) = v1;
        }
        __syncthreads();

        // sparse dot: 2 rows per warp, dual accumulators, zero-padded
        float a0 = 0.0f, a1 = 0.0f;
        for (int k = 0; k < ni; k += 2) {
            Ent e0 = ep[k * 32];
            Ent e1 = ep[k * 32 + 32];
            a0 += e0.v * sh[e0.c];
            a1 += e1.v * sh[e1.c];
        }
        float acc = a0 + a1;
        // allreduce within each 16-lane half
#pragma unroll
        for (int off = 8; off; off >>= 1)
            acc += __shfl_xor_sync(0xffffffffu, acc, off);

        if (head) {
            float xv = acc + __ldg(&g_u[t * RDIM + row]);
            // branch-free tanh: 1 - 2/(e^{2x}+1); saturates correctly at +-inf
            float ex = __expf(2.0f * xv);
            float hv = 1.0f - __fdividef(2.0f, ex + 1.0f);
            __stcg(hn + row, hv);
            float* yb = ybuf[wid * 2 + half];
#pragma unroll
            for (int o = 0; o < ODIM; o++) yb[o] = hv * w_y[o];
        }
        __syncthreads();   // h stores + ybuf visible CTA-wide

        // arrive: release-publish (no L1 flush)
        if (tid == 0) st_rel(&g_flags[blockIdx.x], (unsigned)(t + 1));

        // epilogue hidden in barrier wait: reduce y partials, one atomic per o
        if (tid < ODIM) {
            float s = 0.0f;
#pragma unroll
            for (int j = 0; j < 2 * SLOTS_PER_CTA; j++) s += ybuf[j][tid];
            atomicAdd(out + t * ODIM + tid, s);
        }

        // wait: warp 0 polls all 128 flags with strong (L1-bypass) loads
        if (tid < 32) {
            const unsigned tgt = (unsigned)(t + 1);
            unsigned m;
            do {
                unsigned f0 = ld_acq(&g_flags[tid]);
                unsigned f1 = ld_acq(&g_flags[tid + 32]);
                unsigned f2 = ld_acq(&g_flags[tid + 64]);
                unsigned f3 = ld_acq(&g_flags[tid + 96]);
                m = min(min(f0, f1), min(f2, f3));
            } while (__any_sync(0xffffffffu, m < tgt));
        }
        __syncthreads();
    }
}

// ---------------------------------------------------------------------------
extern "C" void kernel_launch(void* const* d_in, const int* in_sizes, int n_in,
                              void* d_out, int out_size) {
    (void)in_sizes; (void)n_in; (void)out_size;
    const float* x      = (const float*)d_in[0];  // [1, 2048, 8]
    const float* Win    = (const float*)d_in[1];  // [4096, 8]
    const float* W      = (const float*)d_in[2];  // [4096, 4096]
    const float* Wout_w = (const float*)d_in[3];  // [8, 4096]
    const float* Wout_b = (const float*)d_in[4];  // [8]
    float* out = (float*)d_out;                   // [1, 2048, 8]

    k_u<<<TLEN, 256>>>(x, Win);
    k_sparse<<<(RDIM * 32) / 256, 256>>>(W);
    k_init<<<(TLEN * ODIM + 255) / 256, 256>>>(out, Wout_b, Wout_w);
    k_main<<<NBLK, NTHR>>>(out);
}

// round 3
// speedup vs baseline: 1.6112x; 1.6112x over previous
#include <cuda_runtime.h>
#include <cstdint>

// Problem constants (fixed by reference)
#define RDIM 4096
#define TLEN 2048
#define IDIM 8
#define ODIM 8
#define NBLK 128                    // persistent CTAs, co-resident on 148 SMs
#define NTHR 512                    // 16 warps
#define NSLOT (RDIM / 2)            // 2048 warp-slots (2 rows each)
#define SLOTS_PER_CTA 16
#define MAXC 768                    // compacted-row capacity (nnz ~410 +-20)
#define NPAIR_MAX 24                // Ent2 pairs -> 48 sub-iters -> 768/row cap

struct __align__(8)  Ent  { float v; int c; };
struct __align__(16) Ent2 { float v0; int c0; float v1; int c1; };

// Scratch (device globals: no allocation allowed)
__device__ Ent2     g_ellw[NSLOT * NPAIR_MAX * 32];   // ~25 MB bank-scheduled ELL
__device__ Ent      g_rcomp[RDIM * MAXC];             // ~25 MB stage-1 compaction
__device__ int      g_rcnt[RDIM];
__device__ int      g_np[NSLOT];                      // pairs per slot
__device__ float    g_u[TLEN * RDIM];                 // Win @ x_t (32 MB)
__device__ __align__(16) float g_hall[(TLEN + 1) * RDIM];  // all hidden states
__device__ unsigned g_arr[NBLK];                      // barrier counter cells

// L2-direct sync ops: no L1 flush (unlike __threadfence / ld.acquire)
__device__ __forceinline__ unsigned ld_rlx(const unsigned* p) {
    unsigned v;
    asm volatile("ld.relaxed.gpu.global.u32 %0, [%1];" : "=r"(v) : "l"(p) : "memory");
    return v;
}
__device__ __forceinline__ void red_rel_add(unsigned* p) {
    asm volatile("red.release.gpu.global.add.u32 [%0], 1;" :: "l"(p) : "memory");
}

// ---------------------------------------------------------------------------
// K1: u[t][r] = sum_i Win[r,i] * x[t,i]
// ---------------------------------------------------------------------------
__global__ void k_u(const float* __restrict__ x, const float* __restrict__ Win) {
    int t = blockIdx.x;
    __shared__ float xs[IDIM];
    if (threadIdx.x < IDIM) xs[threadIdx.x] = x[t * IDIM + threadIdx.x];
    __syncthreads();
    for (int r = threadIdx.x; r < RDIM; r += blockDim.x) {
        const float4* w = (const float4*)(Win + r * IDIM);
        float4 a = __ldg(&w[0]), b = __ldg(&w[1]);
        g_u[t * RDIM + r] = a.x * xs[0] + a.y * xs[1] + a.z * xs[2] + a.w * xs[3]
                          + b.x * xs[4] + b.y * xs[5] + b.z * xs[6] + b.w * xs[7];
    }
}

// ---------------------------------------------------------------------------
// K2: stage-1 compaction, one warp per row (W zeros are exact).
// ---------------------------------------------------------------------------
__global__ void k_compact(const float* __restrict__ W) {
    int row  = (blockIdx.x * blockDim.x + threadIdx.x) >> 5;
    int lane = threadIdx.x & 31;
    if (row >= RDIM) return;
    const float* wr = W + (size_t)row * RDIM;
    Ent* dst = g_rcomp + (size_t)row * MAXC;
    int cnt = 0;
    for (int c0 = 0; c0 < RDIM; c0 += 32) {
        float v = wr[c0 + lane];
        unsigned bal = __ballot_sync(0xffffffffu, v != 0.0f);
        if (v != 0.0f) {
            int pos = cnt + __popc(bal & ((1u << lane) - 1u));
            if (pos < MAXC) dst[pos] = Ent{v, c0 + lane};
        }
        cnt += __popc(bal);
    }
    if (lane == 0) g_rcnt[row] = cnt < MAXC ? cnt : MAXC;
}

// ---------------------------------------------------------------------------
// K3: bank-conflict-free scheduling. One warp per slot; lane 0 greedily
// assigns each entry to a (sub-iter, lane) pair with a free smem bank.
// Lanes 0-15 serve row 2s; lanes 16-31 serve row 2s+1. Sub-iters 2m,2m+1
// pack into one Ent2 at [m*32 + lane].
// ---------------------------------------------------------------------------
#define NSUB (2 * NPAIR_MAX)
__global__ void k_pack() {
    int wid  = threadIdx.x >> 5;
    int lane = threadIdx.x & 31;
    int slot = blockIdx.x * (blockDim.x / 32) + wid;
    if (slot >= NSLOT) return;

    Ent2* ell = g_ellw + (size_t)slot * (NPAIR_MAX * 32);

    // parallel prefill: v=0, col=lane (self-distinct banks among padding)
    for (int idx = lane; idx < NPAIR_MAX * 32; idx += 32)
        ell[idx] = Ent2{0.0f, idx & 31, 0.0f, idx & 31};
    __syncwarp();

    __shared__ int s_mask[8][NSUB];   // occupied-bank bitmask per sub-iter
    __shared__ int s_cnt[8][2][NSUB]; // filled lanes per half per sub-iter
    if (lane == 0) {
        int kmax = 0;
        for (int k = 0; k < NSUB; k++) {
            s_mask[wid][k] = 0;
            s_cnt[wid][0][k] = 0;
            s_cnt[wid][1][k] = 0;
        }
        for (int half = 0; half < 2; half++) {
            int row = 2 * slot + half;
            int cnt = g_rcnt[row];
            const Ent* src = g_rcomp + (size_t)row * MAXC;
            int base = 0;
            for (int i = 0; i < cnt; i++) {
                Ent e = src[i];
                int b = e.c & 31;
                while (base < NSUB && s_cnt[wid][half][base] >= 16) base++;
                int k = -1;
                for (int kk = base; kk < NSUB; kk++) {
                    if (s_cnt[wid][half][kk] < 16 && !((s_mask[wid][kk] >> b) & 1)) {
                        k = kk; break;
                    }
                }
                if (k < 0) k = base;  // accept conflict (rare)
                int j = s_cnt[wid][half][k];
                s_cnt[wid][half][k] = j + 1;
                s_mask[wid][k] |= 1 << b;
                if (k > kmax) kmax = k;
                Ent2* d = &ell[(k >> 1) * 32 + half * 16 + j];
                if ((k & 1) == 0) { d->v0 = e.v; d->c0 = e.c; }
                else              { d->v1 = e.v; d->c1 = e.c; }
            }
        }
        g_np[slot] = (kmax >> 1) + 1;
    }
}

// ---------------------------------------------------------------------------
// K4: per-replay init
// ---------------------------------------------------------------------------
__global__ void k_init() {
    int i = blockIdx.x * blockDim.x + threadIdx.x;
    if (i < RDIM) g_hall[i] = 0.0f;   // h_0 = 0
    if (i < NBLK) g_arr[i] = 0u;
}

// ---------------------------------------------------------------------------
// K5: persistent recurrence. 128 CTAs x 512 threads, 2 rows/warp (16 lanes
// each). No fences, no acquires: ELL stays L1-resident all 2048 steps.
// ---------------------------------------------------------------------------
__global__ void __launch_bounds__(NTHR, 1)
k_main() {
    __shared__ float sh[RDIM];   // 16 KB: h_{t-1}

    const int tid  = threadIdx.x;
    const int wid  = tid >> 5;
    const int lane = tid & 31;
    const int slot = blockIdx.x * SLOTS_PER_CTA + wid;
    const int half = lane >> 4;
    const int row  = 2 * slot + half;
    const bool head = (lane == 0) | (lane == 16);

    const int   np = g_np[slot];
    const Ent2* ep = g_ellw + (size_t)slot * (NPAIR_MAX * 32) + lane;

    float u_next = head ? __ldg(&g_u[row]) : 0.0f;   // u for t=0

    for (int t = 0; t < TLEN; ++t) {
        const float* hp = g_hall + (size_t)t * RDIM;
        float*       hn = g_hall + (size_t)(t + 1) * RDIM;

        // stage h_{t-1} into SMEM (L2-direct; other CTAs wrote via stcg)
        {
            int i = tid * 4;
            float4 v0 = __ldcg((const float4*)(hp + i));
            float4 v1 = __ldcg((const float4*)(hp + i + NTHR * 4));
            *(float4*)(sh + i) = v0;
            *(float4*)(sh + i + NTHR * 4) = v1;
        }
        __syncthreads();

        // sparse dot: bank-scheduled gathers, 2 entries per lane per iter
        float a0 = 0.0f, a1 = 0.0f;
        for (int k = 0; k < np; k++) {
            Ent2 e = ep[k * 32];
            a0 += e.v0 * sh[e.c0];
            a1 += e.v1 * sh[e.c1];
        }
        float acc = a0 + a1;
#pragma unroll
        for (int off = 8; off; off >>= 1)
            acc += __shfl_xor_sync(0xffffffffu, acc, off);

        if (head) {
            float xv = acc + u_next;
            float ex = __expf(2.0f * xv);               // tanh via exp
            float hv = 1.0f - __fdividef(2.0f, ex + 1.0f);
            __stcg(hn + row, hv);
            // arrive: own release covers own store; no fence, no L1 flush
            red_rel_add(&g_arr[blockIdx.x]);
            if (t + 1 < TLEN) u_next = __ldcg(&g_u[(size_t)(t + 1) * RDIM + row]);
        }

        // wait: warp 0 polls all 128 cells with relaxed L2 loads
        if (tid < 32) {
            const unsigned tgt = 32u * (unsigned)(t + 1);
            for (;;) {
                unsigned m0 = ld_rlx(&g_arr[tid]);
                unsigned m1 = ld_rlx(&g_arr[tid + 32]);
                unsigned m2 = ld_rlx(&g_arr[tid + 64]);
                unsigned m3 = ld_rlx(&g_arr[tid + 96]);
                unsigned m  = min(min(m0, m1), min(m2, m3));
                if (!__any_sync(0xffffffffu, m < tgt)) break;
            }
        }
        __syncthreads();
    }
}

// ---------------------------------------------------------------------------
// K6: out[t][o] = bias[o] + sum_r h_{t+1}[r] * Wout[o][r]
// ---------------------------------------------------------------------------
__global__ void k_out(const float* __restrict__ Wout, const float* __restrict__ bias,
                      float* __restrict__ out) {
    int t = blockIdx.x;
    const float4* h4 = (const float4*)(g_hall + (size_t)(t + 1) * RDIM);
    float acc[ODIM];
#pragma unroll
    for (int o = 0; o < ODIM; o++) acc[o] = 0.0f;

    for (int r4 = threadIdx.x; r4 < RDIM / 4; r4 += blockDim.x) {
        float4 h = h4[r4];
#pragma unroll
        for (int o = 0; o < ODIM; o++) {
            float4 w = __ldg((const float4*)(Wout + o * RDIM) + r4);
            acc[o] += h.x * w.x + h.y * w.y + h.z * w.z + h.w * w.w;
        }
    }
    __shared__ float red[8][ODIM];
    int wid = threadIdx.x >> 5, lane = threadIdx.x & 31;
#pragma unroll
    for (int o = 0; o < ODIM; o++) {
        float v = acc[o];
#pragma unroll
        for (int off = 16; off; off >>= 1)
            v += __shfl_xor_sync(0xffffffffu, v, off);
        if (lane == 0) red[wid][o] = v;
    }
    __syncthreads();
    if (threadIdx.x < ODIM) {
        float s = bias[threadIdx.x];
#pragma unroll
        for (int w = 0; w < 8; w++) s += red[w][threadIdx.x];
        out[t * ODIM + threadIdx.x] = s;
    }
}

// ---------------------------------------------------------------------------
extern "C" void kernel_launch(void* const* d_in, const int* in_sizes, int n_in,
                              void* d_out, int out_size) {
    (void)in_sizes; (void)n_in; (void)out_size;
    const float* x      = (const float*)d_in[0];  // [1, 2048, 8]
    const float* Win    = (const float*)d_in[1];  // [4096, 8]
    const float* W      = (const float*)d_in[2];  // [4096, 4096]
    const float* Wout_w = (const float*)d_in[3];  // [8, 4096]
    const float* Wout_b = (const float*)d_in[4];  // [8]
    float* out = (float*)d_out;                   // [1, 2048, 8]

    k_u<<<TLEN, 256>>>(x, Win);
    k_compact<<<(RDIM * 32) / 256, 256>>>(W);
    k_pack<<<NSLOT / 8, 256>>>();
    k_init<<<(RDIM + 255) / 256, 256>>>();
    k_main<<<NBLK, NTHR>>>();
    k_out<<<TLEN, 256>>>(Wout_w, Wout_b, out);
}